// round 10
// baseline (speedup 1.0000x reference)
#include <cuda_runtime.h>
#include <stdint.h>
#include <math.h>

#define N_PTS   32768
#define KCODES  2048
#define DIM     128
#define BM      128
#define BN      32
#define NTILES  (KCODES / BN)        // 64
#define TEMP_INV (1.0f/0.9f)

// smem float offsets
#define A_S    0                     // 16384 floats: A hi, fragment order (64KB)
#define B_S    16384                 // 2 stages x 4096 floats (32KB)
#define SMEM_FLOATS 24576            // 96KB
// post-mainloop reuse inside B region:
#define RED_V  16384                 // [128][8]
#define RED_I  17408                 // [128][8]
#define SIDX   18432                 // [128]
#define MAXV   18560                 // [128]
#define ZINV   18688                 // [8]
#define BINS   18696                 // [2048]

__device__ float g_conf[(size_t)N_PTS * KCODES];   // 256 MB conf_hh spill
__device__ float g_esq[KCODES];
__device__ float g_clsum[KCODES];
__device__ float g_bhi[KCODES * DIM];              // B tf32-hi, fragment order, tile-major

__device__ __forceinline__ float tf32r(float a) {
    float r; asm("cvt.rna.tf32.f32 %0, %1;" : "=f"(r) : "f"(a)); return r;
}
__device__ __forceinline__ void cp_async16(uint32_t saddr, const void* gptr) {
    asm volatile("cp.async.cg.shared.global [%0], [%1], 16;" :: "r"(saddr), "l"(gptr));
}

#define MMA_TF32(d, a, b) \
    asm volatile("mma.sync.aligned.m16n8k8.row.col.f32.tf32.tf32.f32 " \
        "{%0,%1,%2,%3},{%4,%5,%6,%7},{%8,%9},{%0,%1,%2,%3};" \
        : "+f"((d)[0]), "+f"((d)[1]), "+f"((d)[2]), "+f"((d)[3]) \
        : "r"(__float_as_uint((a)[0])), "r"(__float_as_uint((a)[1])), \
          "r"(__float_as_uint((a)[2])), "r"(__float_as_uint((a)[3])), \
          "r"(__float_as_uint((b)[0])), "r"(__float_as_uint((b)[1])))

// Exact fp32 confidence for one (point, code): 2*dot(x_n, e_k) - esq[k].
// Same fmaf ordering as the R1 kernel that matched the reference exactly.
__device__ __noinline__ float exact_conf(const float* __restrict__ x,
                                         const float* __restrict__ embed,
                                         int n, int k) {
    const float* xr = x + (size_t)n * DIM;
    const float* er = embed + (size_t)k * DIM;
    float s = 0.f;
    #pragma unroll 4
    for (int d = 0; d < DIM; ++d) s = fmaf(xr[d], er[d], s);
    return fmaf(2.f, s, -__ldg(&g_esq[k]));
}

// ---------------------------------------------------------------------------
// Kernel 1: e_sq per code, zero class accumulators, write tf32-hi(embed)
// into MMA fragment order, tile-major (BN=32). (R5-proven mapping.)
// ---------------------------------------------------------------------------
__global__ void prep_kernel(const float* __restrict__ embed) {
    const int tid  = blockIdx.x * blockDim.x + threadIdx.x;  // 0..65535
    const int lane = tid & 31;
    const int warp = tid >> 5;
    if (tid < KCODES) g_clsum[tid] = 0.f;

    {   // e_sq, warp per code
        const float* row = embed + (size_t)warp * DIM;
        float s = 0.f;
        #pragma unroll
        for (int i = 0; i < 4; ++i) { float v = row[lane + 32 * i]; s = fmaf(v, v, s); }
        #pragma unroll
        for (int o = 16; o > 0; o >>= 1) s += __shfl_down_sync(0xffffffffu, s, o);
        if (lane == 0) g_esq[warp] = s;
    }

    {   // B hi fragment-order scatter: one float4 per thread
        float4 v = ((const float4*)embed)[tid];
        const int n   = tid >> 5;
        const int k4  = tid & 31;
        const int ct  = n >> 5;
        const int wn  = (n >> 4) & 1;
        const int nt  = (n >> 3) & 1;
        const int gid = n & 7;
        const int ks  = k4 >> 1;
        const int slot = k4 & 1;
        float a4[4] = {v.x, v.y, v.z, v.w};
        #pragma unroll
        for (int j = 0; j < 4; ++j) {
            size_t o = (size_t)ct * 4096 +
                       ((size_t)(((wn * 2 + nt) * 16 + ks) * 32 + gid * 4 + j)) * 2 + slot;
            g_bhi[o] = tf32r(a4[j]);
        }
    }
}

// ---------------------------------------------------------------------------
// Kernel 2: TF32 hi*hi GEMM (1/3 MMA count) + argmax w/ exact-fp32 rescue +
// fused softmax + gather. 96KB smem -> 2 CTAs/SM, 256 CTAs = 1 wave.
// ---------------------------------------------------------------------------
__global__ void __launch_bounds__(256, 2)
gemm_kernel(const float* __restrict__ x,
            const float* __restrict__ embed,
            float* __restrict__ out_q,
            float* __restrict__ out_ind) {
    extern __shared__ float sm[];

    const int tid  = threadIdx.x;
    const int lane = tid & 31;
    const int w    = tid >> 5;
    const int wm   = w >> 1;          // 0..3: 32-point slab
    const int wn   = w & 1;           // 0..1: 16-code slab
    const int n0   = blockIdx.x * BM;

    const uint32_t b_s = (uint32_t)__cvta_generic_to_shared(sm + B_S);

    // ---- issue B tile 0 copy ----
    {
        const float4* g4 = (const float4*)g_bhi;
        #pragma unroll
        for (int i = 0; i < 4; ++i)
            cp_async16(b_s + (i * 256 + tid) * 16, &g4[i * 256 + tid]);
        asm volatile("cp.async.commit_group;");
    }

    // ---- A hi: tf32(2*x) directly into fragment order ----
    {
        const float4* x4 = (const float4*)(x + (size_t)n0 * DIM);
        #pragma unroll
        for (int t = 0; t < 16; ++t) {
            int idx = t * 256 + tid;
            int m  = idx >> 5;
            int k4 = idx & 31;
            float4 v = x4[idx];
            float a4[4] = {2.f * v.x, 2.f * v.y, 2.f * v.z, 2.f * v.w};
            int r    = m & 15;
            int base = (((m >> 4) * 16 + (k4 >> 1)) * 32) * 4;
            int sl   = (r >> 3) + ((k4 & 1) << 1);
            #pragma unroll
            for (int j = 0; j < 4; ++j)
                sm[A_S + base + ((r & 7) * 4 + j) * 4 + sl] = tf32r(a4[j]);
        }
    }

    float runv[4];
    int   runi[4];
    #pragma unroll
    for (int i = 0; i < 4; ++i) { runv[i] = -3.0e38f; runi[i] = 0; }

    for (int ct = 0; ct < NTILES; ++ct) {
        if (ct + 1 < NTILES) {
            const float4* g4 = (const float4*)(g_bhi + (size_t)(ct + 1) * 4096);
            uint32_t dst = b_s + (uint32_t)(((ct + 1) & 1) * 16384);
            #pragma unroll
            for (int i = 0; i < 4; ++i)
                cp_async16(dst + (i * 256 + tid) * 16, &g4[i * 256 + tid]);
            asm volatile("cp.async.commit_group;");
            asm volatile("cp.async.wait_group 1;");
        } else {
            asm volatile("cp.async.wait_group 0;");
        }
        __syncthreads();                      // stage (ct&1) visible to all warps

        const float* b_hi = sm + B_S + (ct & 1) * 4096;

        float acc[2][2][4];
        #pragma unroll
        for (int mt = 0; mt < 2; ++mt)
            #pragma unroll
            for (int nt = 0; nt < 2; ++nt)
                #pragma unroll
                for (int r = 0; r < 4; ++r) acc[mt][nt][r] = 0.f;

        #pragma unroll
        for (int ks = 0; ks < 16; ++ks) {
            float4 ah4[2];
            #pragma unroll
            for (int mt = 0; mt < 2; ++mt) {
                int ab = (((wm * 2 + mt) * 16 + ks) * 32 + lane) * 4;
                ah4[mt] = *(const float4*)&sm[A_S + ab];
            }
            float2 bh2[2];
            #pragma unroll
            for (int nt = 0; nt < 2; ++nt) {
                int bb = (((wn * 2 + nt) * 16 + ks) * 32 + lane) * 2;
                bh2[nt] = *(const float2*)&b_hi[bb];
            }
            #pragma unroll
            for (int mt = 0; mt < 2; ++mt)
                #pragma unroll
                for (int nt = 0; nt < 2; ++nt)
                    MMA_TF32(acc[mt][nt], (&ah4[mt].x), (&bh2[nt].x));   // hi*hi only
        }

        // ---- epilogue: conf_hh = acc - esq, running argmax, spill ----
        const int c0 = ct * BN;
        #pragma unroll
        for (int nt = 0; nt < 2; ++nt) {
            int cb = c0 + wn * 16 + nt * 8 + 2 * (lane & 3);
            float e0 = __ldg(&g_esq[cb]);
            float e1 = __ldg(&g_esq[cb + 1]);
            #pragma unroll
            for (int mt = 0; mt < 2; ++mt) {
                #pragma unroll
                for (int h = 0; h < 2; ++h) {
                    int slot = mt * 2 + h;
                    int row  = n0 + wm * 32 + mt * 16 + (lane >> 2) + h * 8;
                    float v0 = acc[mt][nt][2 * h + 0] - e0;
                    float v1 = acc[mt][nt][2 * h + 1] - e1;
                    if (v0 > runv[slot]) { runv[slot] = v0; runi[slot] = cb; }
                    if (v1 > runv[slot]) { runv[slot] = v1; runi[slot] = cb + 1; }
                    *(float2*)&g_conf[(size_t)row * KCODES + cb] = make_float2(v0, v1);
                }
            }
        }
        __syncthreads();                      // stage safe to overwrite
    }

    // ---- cross-thread argmax reduction (8 contributors per point) ----
    float* red_v  = sm + RED_V;
    int*   red_i  = (int*)(sm + RED_I);
    int*   sidx   = (int*)(sm + SIDX);
    float* maxv_s = sm + MAXV;
    float* zinv   = sm + ZINV;
    float* bins_s = sm + BINS;
    #pragma unroll
    for (int mt = 0; mt < 2; ++mt)
        #pragma unroll
        for (int h = 0; h < 2; ++h) {
            int slot = mt * 2 + h;
            int rloc = wm * 32 + mt * 16 + (lane >> 2) + h * 8;
            int cidx = wn * 4 + (lane & 3);
            red_v[rloc * 8 + cidx] = runv[slot];
            red_i[rloc * 8 + cidx] = runi[slot];
        }
    __syncthreads();
    if (tid < BM) {
        float bv = red_v[tid * 8];
        int   bi = red_i[tid * 8];
        #pragma unroll
        for (int t = 1; t < 8; ++t) {
            float v  = red_v[tid * 8 + t];
            int   ii = red_i[tid * 8 + t];
            if (v > bv || (v == bv && ii < bi)) { bv = v; bi = ii; }
        }
        maxv_s[tid] = bv;
        sidx[tid]   = bi;
    }
    if (tid < KCODES / 8) {
        #pragma unroll
        for (int r = 0; r < 8; ++r) bins_s[r * 256 + tid] = 0.f;
    }
    __syncthreads();

    // ---- fused softmax on conf_hh (warp per point) + exact-argmax rescue ----
    {
        float* eb = sm + A_S;              // [8][KCODES], A region reused
        for (int it = 0; it < BM / 8; ++it) {
            const int pl = it * 8 + w;
            const float m = maxv_s[pl];
            const int   am = sidx[pl];
            const float thresh = m - 1.0f;
            const float4* row4 = (const float4*)&g_conf[(size_t)(n0 + pl) * KCODES];

            uint32_t cm0 = 0u, cm1 = 0u;   // candidate bitmask over j*4+cc (64 bits)
            float z = 0.f;
            #pragma unroll
            for (int j = 0; j < 16; ++j) {
                int k4 = j * 32 + lane;
                int kb = k4 * 4;
                float4 c = row4[k4];
                float e0 = __expf((c.x - m) * TEMP_INV);
                float e1 = __expf((c.y - m) * TEMP_INV);
                float e2 = __expf((c.z - m) * TEMP_INV);
                float e3 = __expf((c.w - m) * TEMP_INV);
                *(float4*)&eb[w * KCODES + kb] = make_float4(e0, e1, e2, e3);
                z += (e0 + e1) + (e2 + e3);
                uint32_t mbits = 0u;
                if (c.x >= thresh && kb + 0 != am) mbits |= 1u;
                if (c.y >= thresh && kb + 1 != am) mbits |= 2u;
                if (c.z >= thresh && kb + 2 != am) mbits |= 4u;
                if (c.w >= thresh && kb + 3 != am) mbits |= 8u;
                if (j < 8) cm0 |= mbits << (j * 4);
                else       cm1 |= mbits << ((j - 8) * 4);
            }
            #pragma unroll
            for (int o = 16; o > 0; o >>= 1) z += __shfl_xor_sync(0xffffffffu, z, o);
            if (lane == 0) zinv[w] = 1.f / z;

            // rescue: exact fp32 comparison among candidates + current winner
            if (__ballot_sync(0xffffffffu, (cm0 | cm1) != 0u)) {
                float bv; int bi;
                if (lane == 0) { bv = exact_conf(x, embed, n0 + pl, am); bi = am; }
                else           { bv = -3.0e38f; bi = 0x7fffffff; }
                uint32_t mask = cm0;
                while (mask) {
                    int b = __ffs(mask) - 1; mask &= mask - 1;
                    int k = (b >> 2) * 128 + lane * 4 + (b & 3);
                    float v = exact_conf(x, embed, n0 + pl, k);
                    if (v > bv || (v == bv && k < bi)) { bv = v; bi = k; }
                }
                mask = cm1;
                while (mask) {
                    int b = __ffs(mask) - 1; mask &= mask - 1;
                    int k = (b >> 2) * 128 + 1024 + lane * 4 + (b & 3);
                    float v = exact_conf(x, embed, n0 + pl, k);
                    if (v > bv || (v == bv && k < bi)) { bv = v; bi = k; }
                }
                #pragma unroll
                for (int o = 16; o > 0; o >>= 1) {
                    float ov = __shfl_xor_sync(0xffffffffu, bv, o);
                    int   oi = __shfl_xor_sync(0xffffffffu, bi, o);
                    if (ov > bv || (ov == bv && oi < bi)) { bv = ov; bi = oi; }
                }
                if (lane == 0) sidx[pl] = bi;
            }
            __syncthreads();

            for (int k = tid; k < KCODES; k += 256) {
                float s = 0.f;
                #pragma unroll
                for (int ww = 0; ww < 8; ++ww) s = fmaf(eb[ww * KCODES + k], zinv[ww], s);
                bins_s[k] += s;
            }
            __syncthreads();
        }
    }

    // ---- ind write + gather with rescued indices + bins flush ----
    if (tid < BM) out_ind[n0 + tid] = (float)sidx[tid];
    {
        const float4* e4 = (const float4*)embed;
        float4*       q4 = (float4*)out_q;
        for (int p = w; p < BM; p += 8) {
            int idx = sidx[p];
            q4[(size_t)(n0 + p) * 32 + lane] = e4[(size_t)idx * 32 + lane];
        }
    }
    for (int k = tid; k < KCODES; k += 256) atomicAdd(&g_clsum[k], bins_s[k]);
}

// ---------------------------------------------------------------------------
// Kernel 3: diversity loss = sum_k p_k * log(p_k + eps).
// ---------------------------------------------------------------------------
__global__ void loss_kernel(float* __restrict__ out_loss) {
    __shared__ float red[256];
    const int tid = threadIdx.x;
    float acc = 0.f;
    for (int k = tid; k < KCODES; k += 256) {
        float p = g_clsum[k] * (1.0f / (float)N_PTS);
        acc += p * logf(p + 1e-6f);
    }
    red[tid] = acc;
    __syncthreads();
    for (int s = 128; s > 0; s >>= 1) {
        if (tid < s) red[tid] += red[tid + s];
        __syncthreads();
    }
    if (tid == 0) *out_loss = red[0];
}

// ---------------------------------------------------------------------------
extern "C" void kernel_launch(void* const* d_in, const int* in_sizes, int n_in,
                              void* d_out, int out_size) {
    const float* x     = (const float*)d_in[0];
    const float* embed = (const float*)d_in[1];
    float* out      = (float*)d_out;
    float* out_q    = out;                                   // N*DIM
    float* out_ind  = out + (size_t)N_PTS * DIM;             // N
    float* out_loss = out + (size_t)N_PTS * DIM + N_PTS;     // 1

    const int gemm_smem = SMEM_FLOATS * (int)sizeof(float);  // 96 KB
    cudaFuncSetAttribute(gemm_kernel, cudaFuncAttributeMaxDynamicSharedMemorySize, gemm_smem);

    prep_kernel <<<256, 256>>>(embed);
    gemm_kernel <<<N_PTS / BM, 256, gemm_smem>>>(x, embed, out_q, out_ind);
    loss_kernel <<<1, 256>>>(out_loss);
}

// round 11
// speedup vs baseline: 2.2913x; 2.2913x over previous
#include <cuda_runtime.h>
#include <stdint.h>
#include <math.h>

#define N_PTS   32768
#define KCODES  2048
#define DIM     128
#define BM      128
#define BN      32
#define NTILES  (KCODES / BN)        // 64
#define TEMP_INV (1.0f/0.9f)

// smem float offsets
#define A_S    0                     // 16384 floats: A hi, fragment order (64KB)
#define B_S    16384                 // 2 stages x 4096 floats (32KB)
#define SMEM_FLOATS 24576            // 96KB
// post-mainloop reuse inside B region:
#define RED_V  16384                 // [128][8]
#define RED_I  17408                 // [128][8]
#define SIDX   18432                 // [128]
#define MAXV   18560                 // [128]
#define ZINV   18688                 // [8]
#define BINS   18696                 // [2048]

__device__ float g_conf[(size_t)N_PTS * KCODES];   // 256 MB conf_hh spill
__device__ float g_esq[KCODES];
__device__ float g_clsum[KCODES];
__device__ float g_bhi[KCODES * DIM];              // B tf32-hi, fragment order, tile-major

__device__ __forceinline__ float tf32r(float a) {
    float r; asm("cvt.rna.tf32.f32 %0, %1;" : "=f"(r) : "f"(a)); return r;
}
__device__ __forceinline__ void cp_async16(uint32_t saddr, const void* gptr) {
    asm volatile("cp.async.cg.shared.global [%0], [%1], 16;" :: "r"(saddr), "l"(gptr));
}

#define MMA_TF32(d, a, b) \
    asm volatile("mma.sync.aligned.m16n8k8.row.col.f32.tf32.tf32.f32 " \
        "{%0,%1,%2,%3},{%4,%5,%6,%7},{%8,%9},{%0,%1,%2,%3};" \
        : "+f"((d)[0]), "+f"((d)[1]), "+f"((d)[2]), "+f"((d)[3]) \
        : "r"(__float_as_uint((a)[0])), "r"(__float_as_uint((a)[1])), \
          "r"(__float_as_uint((a)[2])), "r"(__float_as_uint((a)[3])), \
          "r"(__float_as_uint((b)[0])), "r"(__float_as_uint((b)[1])))

// Warp-cooperative exact fp32 confidence: 2*dot(x_n, e_k) - esq[k].
// xv = this lane's float4 of the x row (dims lane*4..lane*4+3).
// All lanes return the same value (xor-reduce tree), so comparisons are
// warp-uniform and internally consistent across candidates.
__device__ __forceinline__ float warp_conf(float4 xv, const float* __restrict__ embed,
                                           int k, int lane) {
    float4 ev = ((const float4*)(embed + (size_t)k * DIM))[lane];
    float s = xv.x * ev.x;
    s = fmaf(xv.y, ev.y, s);
    s = fmaf(xv.z, ev.z, s);
    s = fmaf(xv.w, ev.w, s);
    #pragma unroll
    for (int o = 16; o > 0; o >>= 1) s += __shfl_xor_sync(0xffffffffu, s, o);
    return fmaf(2.f, s, -__ldg(&g_esq[k]));
}

// ---------------------------------------------------------------------------
// Kernel 1: e_sq per code, zero class accumulators, write tf32-hi(embed)
// into MMA fragment order, tile-major (BN=32). (R5-proven mapping.)
// ---------------------------------------------------------------------------
__global__ void prep_kernel(const float* __restrict__ embed) {
    const int tid  = blockIdx.x * blockDim.x + threadIdx.x;  // 0..65535
    const int lane = tid & 31;
    const int warp = tid >> 5;
    if (tid < KCODES) g_clsum[tid] = 0.f;

    {   // e_sq, warp per code
        const float* row = embed + (size_t)warp * DIM;
        float s = 0.f;
        #pragma unroll
        for (int i = 0; i < 4; ++i) { float v = row[lane + 32 * i]; s = fmaf(v, v, s); }
        #pragma unroll
        for (int o = 16; o > 0; o >>= 1) s += __shfl_down_sync(0xffffffffu, s, o);
        if (lane == 0) g_esq[warp] = s;
    }

    {   // B hi fragment-order scatter: one float4 per thread
        float4 v = ((const float4*)embed)[tid];
        const int n   = tid >> 5;
        const int k4  = tid & 31;
        const int ct  = n >> 5;
        const int wn  = (n >> 4) & 1;
        const int nt  = (n >> 3) & 1;
        const int gid = n & 7;
        const int ks  = k4 >> 1;
        const int slot = k4 & 1;
        float a4[4] = {v.x, v.y, v.z, v.w};
        #pragma unroll
        for (int j = 0; j < 4; ++j) {
            size_t o = (size_t)ct * 4096 +
                       ((size_t)(((wn * 2 + nt) * 16 + ks) * 32 + gid * 4 + j)) * 2 + slot;
            g_bhi[o] = tf32r(a4[j]);
        }
    }
}

// ---------------------------------------------------------------------------
// Kernel 2: TF32 hi*hi GEMM (1/3 MMA count) + argmax w/ warp-cooperative
// exact rescue + fused softmax + gather. 96KB smem -> 2 CTAs/SM, 1 wave.
// ---------------------------------------------------------------------------
__global__ void __launch_bounds__(256, 2)
gemm_kernel(const float* __restrict__ x,
            const float* __restrict__ embed,
            float* __restrict__ out_q,
            float* __restrict__ out_ind) {
    extern __shared__ float sm[];

    const int tid  = threadIdx.x;
    const int lane = tid & 31;
    const int w    = tid >> 5;
    const int wm   = w >> 1;          // 0..3: 32-point slab
    const int wn   = w & 1;           // 0..1: 16-code slab
    const int n0   = blockIdx.x * BM;

    const uint32_t b_s = (uint32_t)__cvta_generic_to_shared(sm + B_S);

    // ---- issue B tile 0 copy ----
    {
        const float4* g4 = (const float4*)g_bhi;
        #pragma unroll
        for (int i = 0; i < 4; ++i)
            cp_async16(b_s + (i * 256 + tid) * 16, &g4[i * 256 + tid]);
        asm volatile("cp.async.commit_group;");
    }

    // ---- A hi: tf32(2*x) directly into fragment order ----
    {
        const float4* x4 = (const float4*)(x + (size_t)n0 * DIM);
        #pragma unroll
        for (int t = 0; t < 16; ++t) {
            int idx = t * 256 + tid;
            int m  = idx >> 5;
            int k4 = idx & 31;
            float4 v = x4[idx];
            float a4[4] = {2.f * v.x, 2.f * v.y, 2.f * v.z, 2.f * v.w};
            int r    = m & 15;
            int base = (((m >> 4) * 16 + (k4 >> 1)) * 32) * 4;
            int sl   = (r >> 3) + ((k4 & 1) << 1);
            #pragma unroll
            for (int j = 0; j < 4; ++j)
                sm[A_S + base + ((r & 7) * 4 + j) * 4 + sl] = tf32r(a4[j]);
        }
    }

    float runv[4];
    int   runi[4];
    #pragma unroll
    for (int i = 0; i < 4; ++i) { runv[i] = -3.0e38f; runi[i] = 0; }

    for (int ct = 0; ct < NTILES; ++ct) {
        if (ct + 1 < NTILES) {
            const float4* g4 = (const float4*)(g_bhi + (size_t)(ct + 1) * 4096);
            uint32_t dst = b_s + (uint32_t)(((ct + 1) & 1) * 16384);
            #pragma unroll
            for (int i = 0; i < 4; ++i)
                cp_async16(dst + (i * 256 + tid) * 16, &g4[i * 256 + tid]);
            asm volatile("cp.async.commit_group;");
            asm volatile("cp.async.wait_group 1;");
        } else {
            asm volatile("cp.async.wait_group 0;");
        }
        __syncthreads();                      // stage (ct&1) visible to all warps

        const float* b_hi = sm + B_S + (ct & 1) * 4096;

        float acc[2][2][4];
        #pragma unroll
        for (int mt = 0; mt < 2; ++mt)
            #pragma unroll
            for (int nt = 0; nt < 2; ++nt)
                #pragma unroll
                for (int r = 0; r < 4; ++r) acc[mt][nt][r] = 0.f;

        #pragma unroll
        for (int ks = 0; ks < 16; ++ks) {
            float4 ah4[2];
            #pragma unroll
            for (int mt = 0; mt < 2; ++mt) {
                int ab = (((wm * 2 + mt) * 16 + ks) * 32 + lane) * 4;
                ah4[mt] = *(const float4*)&sm[A_S + ab];
            }
            float2 bh2[2];
            #pragma unroll
            for (int nt = 0; nt < 2; ++nt) {
                int bb = (((wn * 2 + nt) * 16 + ks) * 32 + lane) * 2;
                bh2[nt] = *(const float2*)&b_hi[bb];
            }
            #pragma unroll
            for (int mt = 0; mt < 2; ++mt)
                #pragma unroll
                for (int nt = 0; nt < 2; ++nt)
                    MMA_TF32(acc[mt][nt], (&ah4[mt].x), (&bh2[nt].x));   // hi*hi only
        }

        // ---- epilogue: conf_hh = acc - esq, running argmax, spill ----
        const int c0 = ct * BN;
        #pragma unroll
        for (int nt = 0; nt < 2; ++nt) {
            int cb = c0 + wn * 16 + nt * 8 + 2 * (lane & 3);
            float e0 = __ldg(&g_esq[cb]);
            float e1 = __ldg(&g_esq[cb + 1]);
            #pragma unroll
            for (int mt = 0; mt < 2; ++mt) {
                #pragma unroll
                for (int h = 0; h < 2; ++h) {
                    int slot = mt * 2 + h;
                    int row  = n0 + wm * 32 + mt * 16 + (lane >> 2) + h * 8;
                    float v0 = acc[mt][nt][2 * h + 0] - e0;
                    float v1 = acc[mt][nt][2 * h + 1] - e1;
                    if (v0 > runv[slot]) { runv[slot] = v0; runi[slot] = cb; }
                    if (v1 > runv[slot]) { runv[slot] = v1; runi[slot] = cb + 1; }
                    *(float2*)&g_conf[(size_t)row * KCODES + cb] = make_float2(v0, v1);
                }
            }
        }
        __syncthreads();                      // stage safe to overwrite
    }

    // ---- cross-thread argmax reduction (8 contributors per point) ----
    float* red_v  = sm + RED_V;
    int*   red_i  = (int*)(sm + RED_I);
    int*   sidx   = (int*)(sm + SIDX);
    float* maxv_s = sm + MAXV;
    float* zinv   = sm + ZINV;
    float* bins_s = sm + BINS;
    #pragma unroll
    for (int mt = 0; mt < 2; ++mt)
        #pragma unroll
        for (int h = 0; h < 2; ++h) {
            int slot = mt * 2 + h;
            int rloc = wm * 32 + mt * 16 + (lane >> 2) + h * 8;
            int cidx = wn * 4 + (lane & 3);
            red_v[rloc * 8 + cidx] = runv[slot];
            red_i[rloc * 8 + cidx] = runi[slot];
        }
    __syncthreads();
    if (tid < BM) {
        float bv = red_v[tid * 8];
        int   bi = red_i[tid * 8];
        #pragma unroll
        for (int t = 1; t < 8; ++t) {
            float v  = red_v[tid * 8 + t];
            int   ii = red_i[tid * 8 + t];
            if (v > bv || (v == bv && ii < bi)) { bv = v; bi = ii; }
        }
        maxv_s[tid] = bv;
        sidx[tid]   = bi;
    }
    if (tid < KCODES / 8) {
        #pragma unroll
        for (int r = 0; r < 8; ++r) bins_s[r * 256 + tid] = 0.f;
    }
    __syncthreads();

    // ---- fused softmax on conf_hh (warp per point) + warp-coop exact rescue ----
    {
        float* eb = sm + A_S;              // [8][KCODES], A region reused
        for (int it = 0; it < BM / 8; ++it) {
            const int pl = it * 8 + w;
            const float m = maxv_s[pl];
            const int   am = sidx[pl];
            const float thresh = m - 1.0f;
            const float4* row4 = (const float4*)&g_conf[(size_t)(n0 + pl) * KCODES];

            uint32_t cm0 = 0u, cm1 = 0u;   // candidate bitmask over j*4+cc (64 bits)
            float z = 0.f;
            #pragma unroll
            for (int j = 0; j < 16; ++j) {
                int k4 = j * 32 + lane;
                int kb = k4 * 4;
                float4 c = row4[k4];
                float e0 = __expf((c.x - m) * TEMP_INV);
                float e1 = __expf((c.y - m) * TEMP_INV);
                float e2 = __expf((c.z - m) * TEMP_INV);
                float e3 = __expf((c.w - m) * TEMP_INV);
                *(float4*)&eb[w * KCODES + kb] = make_float4(e0, e1, e2, e3);
                z += (e0 + e1) + (e2 + e3);
                uint32_t mbits = 0u;
                if (c.x >= thresh && kb + 0 != am) mbits |= 1u;
                if (c.y >= thresh && kb + 1 != am) mbits |= 2u;
                if (c.z >= thresh && kb + 2 != am) mbits |= 4u;
                if (c.w >= thresh && kb + 3 != am) mbits |= 8u;
                if (j < 8) cm0 |= mbits << (j * 4);
                else       cm1 |= mbits << ((j - 8) * 4);
            }
            #pragma unroll
            for (int o = 16; o > 0; o >>= 1) z += __shfl_xor_sync(0xffffffffu, z, o);
            if (lane == 0) zinv[w] = 1.f / z;

            // rescue: warp-cooperative exact fp32 comparison among candidates
            if (__ballot_sync(0xffffffffu, (cm0 | cm1) != 0u) != 0u) {
                float4 xv = ((const float4*)(x + (size_t)(n0 + pl) * DIM))[lane];
                float bv = warp_conf(xv, embed, am, lane);   // exact winner value
                int   bi = am;
                for (;;) {
                    uint32_t have = __ballot_sync(0xffffffffu, (cm0 | cm1) != 0u);
                    if (!have) break;
                    int src = __ffs(have) - 1;
                    int kc = 0;
                    if (lane == src) {
                        if (cm0) {
                            int b = __ffs(cm0) - 1; cm0 &= cm0 - 1;
                            kc = (b >> 2) * 128 + lane * 4 + (b & 3);
                        } else {
                            int b = __ffs(cm1) - 1; cm1 &= cm1 - 1;
                            kc = (b >> 2) * 128 + 1024 + lane * 4 + (b & 3);
                        }
                    }
                    kc = __shfl_sync(0xffffffffu, kc, src);
                    float v = warp_conf(xv, embed, kc, lane);
                    if (v > bv || (v == bv && kc < bi)) { bv = v; bi = kc; }
                }
                if (lane == 0) sidx[pl] = bi;
            }
            __syncthreads();

            for (int k = tid; k < KCODES; k += 256) {
                float s = 0.f;
                #pragma unroll
                for (int ww = 0; ww < 8; ++ww) s = fmaf(eb[ww * KCODES + k], zinv[ww], s);
                bins_s[k] += s;
            }
            __syncthreads();
        }
    }

    // ---- ind write + gather with rescued indices + bins flush ----
    if (tid < BM) out_ind[n0 + tid] = (float)sidx[tid];
    {
        const float4* e4 = (const float4*)embed;
        float4*       q4 = (float4*)out_q;
        for (int p = w; p < BM; p += 8) {
            int idx = sidx[p];
            q4[(size_t)(n0 + p) * 32 + lane] = e4[(size_t)idx * 32 + lane];
        }
    }
    for (int k = tid; k < KCODES; k += 256) atomicAdd(&g_clsum[k], bins_s[k]);
}

// ---------------------------------------------------------------------------
// Kernel 3: diversity loss = sum_k p_k * log(p_k + eps).
// ---------------------------------------------------------------------------
__global__ void loss_kernel(float* __restrict__ out_loss) {
    __shared__ float red[256];
    const int tid = threadIdx.x;
    float acc = 0.f;
    for (int k = tid; k < KCODES; k += 256) {
        float p = g_clsum[k] * (1.0f / (float)N_PTS);
        acc += p * logf(p + 1e-6f);
    }
    red[tid] = acc;
    __syncthreads();
    for (int s = 128; s > 0; s >>= 1) {
        if (tid < s) red[tid] += red[tid + s];
        __syncthreads();
    }
    if (tid == 0) *out_loss = red[0];
}

// ---------------------------------------------------------------------------
extern "C" void kernel_launch(void* const* d_in, const int* in_sizes, int n_in,
                              void* d_out, int out_size) {
    const float* x     = (const float*)d_in[0];
    const float* embed = (const float*)d_in[1];
    float* out      = (float*)d_out;
    float* out_q    = out;                                   // N*DIM
    float* out_ind  = out + (size_t)N_PTS * DIM;             // N
    float* out_loss = out + (size_t)N_PTS * DIM + N_PTS;     // 1

    const int gemm_smem = SMEM_FLOATS * (int)sizeof(float);  // 96 KB
    cudaFuncSetAttribute(gemm_kernel, cudaFuncAttributeMaxDynamicSharedMemorySize, gemm_smem);

    prep_kernel <<<256, 256>>>(embed);
    gemm_kernel <<<N_PTS / BM, 256, gemm_smem>>>(x, embed, out_q, out_ind);
    loss_kernel <<<1, 256>>>(out_loss);
}